// round 15
// baseline (speedup 1.0000x reference)
#include <cuda_runtime.h>
#include <cuda.h>
#include <stdint.h>

// Problem constants
#define Bn 8
#define Sn 1024
#define En 768
#define Hn 12
#define F3 2304          // 3*E
#define NQKV 27648       // H*3E
#define HE 9216          // H*E

// Scratch (allocation-free: __device__ globals)
__device__ float g_qkv[(size_t)Bn * Hn * Sn * F3];     // [B,H,S,3E] (Q,K slabs used)
__device__ float g_scores[(size_t)Bn * Hn * Sn * Sn];  // [B*H,S,S]
__device__ float g_vT[(size_t)Bn * Hn * En * Sn];      // [B*H,E,S]  (tf32-rounded)
__device__ float g_concat[(size_t)Bn * Sn * Hn * En];  // [B,S,H,E]  (tf32-rounded)
__device__ float g_xr[(size_t)Bn * Sn * En];           // rounded x
__device__ float g_wqkvr[(size_t)NQKV * En];           // rounded qkv_w
__device__ float g_owr[(size_t)En * HE];               // rounded out_w

struct GemmParams {
    const float* A;
    const float* B;
    float* C;
    int K;
    int lda, ldb, ldc;
    long long strideAz, strideBz;
    long long strideCb, strideCh;
    int divH;
    const float* bias;
    float alpha;
};

__device__ __forceinline__ uint32_t f2tf32(float x) {
    uint32_t r;
    asm("cvt.rna.tf32.f32 %0, %1;" : "=r"(r) : "f"(x));
    return r;
}

__device__ __forceinline__ uint32_t smem_u32_g(const void* p) {
    uint32_t a;
    asm("{ .reg .u64 t; cvta.to.shared.u64 t, %1; cvt.u32.u64 %0, t; }"
        : "=r"(a) : "l"(p));
    return a;
}

#if defined(__CUDA_ARCH_FEAT_SM103_ALL)
// ---------- sm_103a-only helpers ----------
__device__ __forceinline__ uint32_t elect_one() {
    uint32_t p;
    asm volatile(
        "{\n\t.reg .pred p;\n\telect.sync _|p, 0xFFFFFFFF;\n\t"
        "selp.b32 %0, 1, 0, p;\n\t}" : "=r"(p));
    return p;
}

#define TCGEN05_ALLOC(a, n) \
    asm volatile("tcgen05.alloc.cta_group::1.sync.aligned.shared::cta.b32 [%0], %1;" \
                 :: "r"(a), "r"(n) : "memory")
#define TCGEN05_DEALLOC(t, n) \
    asm volatile("tcgen05.dealloc.cta_group::1.sync.aligned.b32 %0, %1;" :: "r"(t), "r"(n))
#define TCGEN05_RELINQ() \
    asm volatile("tcgen05.relinquish_alloc_permit.cta_group::1.sync.aligned;")
#define TCGEN05_COMMIT(m) \
    asm volatile("tcgen05.commit.cta_group::1.mbarrier::arrive::one.shared::cluster.b64 [%0];" \
                 :: "r"(m) : "memory")
#define MBARRIER_INIT(m, c) \
    asm volatile("mbarrier.init.shared.b64 [%0], %1;" :: "r"(m), "r"(c) : "memory")
#define MBARRIER_INVAL(m) \
    asm volatile("mbarrier.inval.shared.b64 [%0];" :: "r"(m) : "memory")
#define MBARRIER_EXPECT_TX(m, b) \
    asm volatile("mbarrier.arrive.expect_tx.shared.b64 _, [%0], %1;" \
                 :: "r"(m), "r"(b) : "memory")
#define TCGEN05_FENCE_AFTER()  asm volatile("tcgen05.fence::after_thread_sync;" ::: "memory")
#define TCGEN05_FENCE_BEFORE() asm volatile("tcgen05.fence::before_thread_sync;" ::: "memory")
#define TCGEN05_WAIT_LD()      asm volatile("tcgen05.wait::ld.sync.aligned;" ::: "memory")
#define FENCE_ASYNC()          asm volatile("fence.proxy.async.shared::cta;" ::: "memory")

#define TMA3D(sm, mapp, cx, cy, cz, mb) \
    asm volatile( \
        "cp.async.bulk.tensor.3d.shared::cta.global.tile.mbarrier::complete_tx::bytes " \
        "[%0], [%1, {%2, %3, %4}], [%5];" \
        :: "r"(sm), "l"(mapp), "r"(cx), "r"(cy), "r"(cz), "r"(mb) : "memory")

#define MBARRIER_WAIT_PARITY(mbar_smem_addr, phase_parity) do { \
    uint32_t _mbar = (uint32_t)(mbar_smem_addr); \
    uint32_t _parity = (uint32_t)(phase_parity); \
    uint32_t _done; \
    asm volatile( \
        "{\n\t.reg .pred p;\n\t" \
        "mbarrier.try_wait.parity.acquire.cta.shared::cta.b64 p, [%1], %2;\n\t" \
        "selp.b32 %0, 1, 0, p;\n\t}" \
        : "=r"(_done) : "r"(_mbar), "r"(_parity) : "memory"); \
    if (!_done) { \
        asm volatile( \
            "{\n\t.reg .pred P1;\n\t" \
            "WAIT_LOOP_%=:\n\t" \
            "mbarrier.try_wait.parity.acquire.cta.shared::cta.b64 P1, [%0], %1, 0x989680;\n\t" \
            "@P1 bra.uni WAIT_DONE_%=;\n\t" \
            "bra.uni WAIT_LOOP_%=;\n\t" \
            "WAIT_DONE_%=:\n\t}" \
            :: "r"(_mbar), "r"(_parity) : "memory"); \
    } \
} while (0)

#define TCGEN05_LD_32X32B_X32(r, tmem_addr) \
    asm volatile( \
        "tcgen05.ld.sync.aligned.32x32b.x32.b32 " \
        "{%0, %1, %2, %3, %4, %5, %6, %7, " \
        " %8, %9, %10, %11, %12, %13, %14, %15, " \
        " %16, %17, %18, %19, %20, %21, %22, %23, " \
        " %24, %25, %26, %27, %28, %29, %30, %31}, [%32];" \
        : "=r"((r)[0]),  "=r"((r)[1]),  "=r"((r)[2]),  "=r"((r)[3]), \
          "=r"((r)[4]),  "=r"((r)[5]),  "=r"((r)[6]),  "=r"((r)[7]), \
          "=r"((r)[8]),  "=r"((r)[9]),  "=r"((r)[10]), "=r"((r)[11]), \
          "=r"((r)[12]), "=r"((r)[13]), "=r"((r)[14]), "=r"((r)[15]), \
          "=r"((r)[16]), "=r"((r)[17]), "=r"((r)[18]), "=r"((r)[19]), \
          "=r"((r)[20]), "=r"((r)[21]), "=r"((r)[22]), "=r"((r)[23]), \
          "=r"((r)[24]), "=r"((r)[25]), "=r"((r)[26]), "=r"((r)[27]), \
          "=r"((r)[28]), "=r"((r)[29]), "=r"((r)[30]), "=r"((r)[31]) \
        : "r"(tmem_addr))

// SW128 K-major SMEM descriptor (128B rows): layout=SW128, version=1, SBO=64, LBO=1
static __device__ __forceinline__ uint64_t mk_desc(uint32_t addr) {
    const uint64_t base = (2ULL << 61) | (1ULL << 46) | (64ULL << 32) | (1ULL << 16);
    return base | ((uint64_t)(addr >> 4) & 0x3FFF);
}

// idesc kind::tf32: dtype F32=1 @bit4, atype=btype=TF32=2 @bits7/10,
// N/8 @bit17, M/16 @bit24   (M=128, N=256)
#define IDESC_TF32 ((1u << 4) | (2u << 7) | (2u << 10) | (32u << 17) | (8u << 24))

__device__ __forceinline__ void mma_tf32_ss(uint32_t d_tmem, uint64_t ad, uint64_t bd,
                                            uint32_t en) {
    asm volatile(
        "{\n\t.reg .pred pq;\n\tsetp.ne.u32 pq, %5, 0;\n\t"
        "tcgen05.mma.cta_group::1.kind::tf32 [%0], %1, %2, %3, {%4, %4, %4, %4}, pq;\n\t}"
        :: "r"(d_tmem), "l"(ad), "l"(bd), "r"(IDESC_TF32), "r"(0u), "r"(en)
        : "memory");
}
#endif  // __CUDA_ARCH_FEAT_SM103_ALL

// ---------- GEMM: A[M,K] x B[N,K]^T, tile 128x256, 256 threads ----------
// sm_103a: TMA-fed NS-stage ring tcgen05 SS pipeline. 96KB SMEM -> 2 CTAs/SM:
// one CTA's prologue/epilogue/mbarrier stalls overlap the co-resident CTA's
// MMAs (the async engines do the heavy lifting; SMSPs are mostly idle).
// SWAP=1: bm on blockIdx.x (wave spans M tiles -> B streamed from DRAM once).
// Epilogue: TMEM slices staged via padded SMEM -> coalesced 128B row stores.
// EPI=1 (QKV): Q/K slices scatter to g_qkv; V slices written TRANSPOSED to g_vT.
template <int NS, int EPI, int ROUND, int SWAP>
__global__ void __launch_bounds__(256, 2) gemm_tma(
    const __grid_constant__ CUtensorMap mA,
    const __grid_constant__ CUtensorMap mB,
    GemmParams p)
{
    extern __shared__ __align__(16) float smem_raw[];
    const int tid = threadIdx.x;
    const int lane = tid & 31;
    const int wid = tid >> 5;
    const int bn = SWAP ? blockIdx.y : blockIdx.x;
    const int bm = SWAP ? blockIdx.x : blockIdx.y;
    const int z  = blockIdx.z;
    const size_t coff = (size_t)(z / p.divH) * p.strideCb +
                        (size_t)(z % p.divH) * p.strideCh;

#if defined(__CUDA_ARCH_FEAT_SM103_ALL)
    __shared__ uint32_t s_tmem;
    __shared__ __align__(8) unsigned long long s_mbar[2 * NS];  // full[NS], done[NS]

    const uint32_t raw_u  = smem_u32_g(smem_raw);
    const uint32_t smem_u = (raw_u + 1023u) & ~1023u;   // SW128 atom alignment
    float* smem_al = (float*)((char*)smem_raw + (smem_u - raw_u));
    const uint32_t mbar   = smem_u32_g(s_mbar);

    constexpr uint32_t ASZ = 16384u;            // A stage bytes (128 rows x 128B)
    constexpr uint32_t SZ  = ASZ + 32768u;      // stage bytes (A+B) = 48KB

    if (wid == 0) { TCGEN05_ALLOC(smem_u32_g(&s_tmem), 256); TCGEN05_RELINQ(); }
    if (tid == 0) {
        #pragma unroll
        for (int s = 0; s < 2 * NS; s++) MBARRIER_INIT(mbar + 8 * s, 1);
        FENCE_ASYNC();
    }
    __syncthreads();
    const uint32_t tmem = s_tmem;

    const int nIter = p.K >> 5;   // 24 / 32 / 288

    if (wid == 0) {
        if (elect_one()) {
            const CUtensorMap* pA = &mA;
            const CUtensorMap* pB = &mB;
            const int m0 = bm * 128;
            const int n0 = bn * 256;
            int phf[NS], phd[NS];
            #pragma unroll
            for (int s = 0; s < NS; s++) { phf[s] = 0; phd[s] = 0; }

            const int pre = (nIter < NS) ? nIter : NS;
            for (int s = 0; s < pre; s++) {
                MBARRIER_EXPECT_TX(mbar + 8 * s, SZ);
                TMA3D(smem_u + s * SZ, pA, s * 32, m0, z, mbar + 8 * s);
                TMA3D(smem_u + s * SZ + ASZ, pB, s * 32, n0, z, mbar + 8 * s);
            }

            for (int kt = 0; kt < nIter; kt++) {
                const int b = kt % NS;
                MBARRIER_WAIT_PARITY(mbar + 8 * b, phf[b]); phf[b] ^= 1;
                const uint32_t oa = smem_u + b * SZ;
                const uint64_t ad = mk_desc(oa);
                const uint64_t bd = mk_desc(oa + ASZ);
                #pragma unroll
                for (int ks = 0; ks < 4; ks++)
                    mma_tf32_ss(tmem, ad + ks * 2, bd + ks * 2,
                                (kt > 0 || ks > 0) ? 1u : 0u);
                TCGEN05_COMMIT(mbar + 8 * (NS + b));
                const int rt = kt - 1;
                if (rt >= 0 && rt + NS < nIter) {
                    const int rb = rt % NS;
                    MBARRIER_WAIT_PARITY(mbar + 8 * (NS + rb), phd[rb]); phd[rb] ^= 1;
                    const uint32_t ra = smem_u + rb * SZ;
                    MBARRIER_EXPECT_TX(mbar + 8 * rb, SZ);
                    TMA3D(ra, pA, (rt + NS) * 32, m0, z, mbar + 8 * rb);
                    TMA3D(ra + ASZ, pB, (rt + NS) * 32, n0, z, mbar + 8 * rb);
                }
            }
            int first = nIter - NS;
            if (first < 0) first = 0;
            for (int kt = first; kt < nIter; kt++) {
                const int b = kt % NS;
                MBARRIER_WAIT_PARITY(mbar + 8 * (NS + b), phd[b]); phd[b] ^= 1;
            }
        }
    }
    __syncthreads();
    TCGEN05_FENCE_AFTER();

    // ---- Coalesced epilogue via padded SMEM staging ----
    // Warps 0-3: cols 0-127; warps 4-7: cols 128-255. 4 slices of 32 cols.
    const int mrow0 = bm * 128 + (wid & 3) * 32;
    const uint32_t tbase = tmem + (uint32_t)(wid >> 2) * 128u;
    const int nbase = bn * 256 + (wid >> 2) * 128;
    float* stg = smem_al + wid * (33 * 32);

    for (int i = 0; i < 4; i++) {
        uint32_t r[32];
        TCGEN05_LD_32X32B_X32(r, tbase + i * 32);
        TCGEN05_WAIT_LD();
        #pragma unroll
        for (int j = 0; j < 32; j++) stg[lane * 33 + j] = __uint_as_float(r[j]);
        __syncwarp();

        const int n0 = nbase + i * 32;

        if (EPI == 1) {
            const int b = mrow0 >> 10, s = mrow0 & 1023;
            const int h = n0 / F3, f = n0 - h * F3;
            if (f >= 2 * En) {
                // V slice: write transposed into g_vT[bh][e][s] (coalesced rows)
                float* dstv = g_vT + (((size_t)(b * Hn + h)) * En + (f - 2 * En)) * Sn + s;
                #pragma unroll 8
                for (int row = 0; row < 32; row++) {
                    float bia = p.bias ? __ldg(&p.bias[n0 + row]) : 0.f;
                    float v = stg[lane * 33 + row] * p.alpha + bia;
                    if (ROUND) v = __uint_as_float(f2tf32(v));
                    dstv[(size_t)row * Sn + lane] = v;
                }
                __syncwarp();
                continue;
            }
        }

        const float bia = p.bias ? __ldg(&p.bias[n0 + lane]) : 0.f;
        float* dst0;
        long long rstride;
        if (EPI == 1) {
            const int b = mrow0 >> 10, s = mrow0 & 1023;
            const int h = n0 / F3, f = n0 - h * F3;
            dst0 = &g_qkv[(((size_t)(b * Hn + h)) * Sn + s) * F3 + f];
            rstride = F3;
        } else {
            dst0 = &p.C[coff + (size_t)mrow0 * p.ldc + n0];
            rstride = p.ldc;
        }
        #pragma unroll 8
        for (int row = 0; row < 32; row++) {
            float v = stg[row * 33 + lane] * p.alpha + bia;
            if (ROUND) v = __uint_as_float(f2tf32(v));
            dst0[(size_t)row * rstride + lane] = v;
        }
        __syncwarp();
    }
    TCGEN05_FENCE_BEFORE();

    __syncthreads();
    if (tid == 0) {
        #pragma unroll
        for (int s = 0; s < 2 * NS; s++) MBARRIER_INVAL(mbar + 8 * s);
    }
    __syncthreads();
    if (wid == 0) TCGEN05_DEALLOC(tmem, 256);

#else
    // Naive correct fallback (never selected when sm_103a SASS is present)
    (void)smem_raw;
    for (int o = tid; o < 128 * 256; o += 256) {
        const int mi = o >> 8;
        const int ni = o & 255;
        const float* a = p.A + (size_t)z * p.strideAz + (size_t)(bm * 128 + mi) * p.lda;
        const float* b = p.B + (size_t)z * p.strideBz + (size_t)(bn * 256 + ni) * p.ldb;
        float acc = 0.f;
        for (int k = 0; k < p.K; k++) acc += a[k] * b[k];
        float v = acc * p.alpha;
        const int n0 = bn * 256 + ni;
        if (p.bias) v += p.bias[n0];
        if (ROUND) v = __uint_as_float(f2tf32(v));
        const int mg = bm * 128 + mi;
        if (EPI == 1) {
            const int bb = mg >> 10, s = mg & 1023;
            const int h = n0 / F3, f = n0 - h * F3;
            if (f >= 2 * En)
                g_vT[(((size_t)(bb * Hn + h)) * En + (f - 2 * En)) * Sn + s] = v;
            else
                g_qkv[(((size_t)(bb * Hn + h)) * Sn + s) * F3 + f] = v;
        } else {
            p.C[coff + (size_t)mg * p.ldc + n0] = v;
        }
    }
#endif
}

// Round-copy: dst = tf32_rna(src)
__global__ void __launch_bounds__(256) round_copy(const float* __restrict__ s,
                                                  float* __restrict__ d, int n4)
{
    int i = blockIdx.x * blockDim.x + threadIdx.x;
    if (i < n4) {
        float4 v = ((const float4*)s)[i];
        uint4 o;
        o.x = f2tf32(v.x); o.y = f2tf32(v.y); o.z = f2tf32(v.z); o.w = f2tf32(v.w);
        ((uint4*)d)[i] = o;
    }
}

// Softmax rows; output rounded to tf32 bits (AV GEMM input).
__global__ void __launch_bounds__(256) softmax_kernel(float* sc)
{
    float* row = sc + (size_t)blockIdx.x * Sn;
    const int tid = threadIdx.x;
    const int lane = tid & 31;
    const int wid = tid >> 5;
    __shared__ float red[8];

    float4 v = ((const float4*)row)[tid];
    float m = fmaxf(fmaxf(v.x, v.y), fmaxf(v.z, v.w));
    #pragma unroll
    for (int o = 16; o; o >>= 1) m = fmaxf(m, __shfl_xor_sync(~0u, m, o));
    if (lane == 0) red[wid] = m;
    __syncthreads();
    float bm = red[0];
    #pragma unroll
    for (int i = 1; i < 8; i++) bm = fmaxf(bm, red[i]);
    __syncthreads();

    float4 e;
    e.x = __expf(v.x - bm);
    e.y = __expf(v.y - bm);
    e.z = __expf(v.z - bm);
    e.w = __expf(v.w - bm);
    float s = e.x + e.y + e.z + e.w;
    #pragma unroll
    for (int o = 16; o; o >>= 1) s += __shfl_xor_sync(~0u, s, o);
    if (lane == 0) red[wid] = s;
    __syncthreads();
    float bs = red[0];
    #pragma unroll
    for (int i = 1; i < 8; i++) bs += red[i];
    const float rdiv = __frcp_rn(bs);

    uint4 o;
    o.x = f2tf32(e.x * rdiv);
    o.y = f2tf32(e.y * rdiv);
    o.z = f2tf32(e.z * rdiv);
    o.w = f2tf32(e.w * rdiv);
    ((uint4*)row)[tid] = o;
}

#define SMEM_RING (98304 + 1024)   // 2 stages x 48KB + align slack -> 2 CTAs/SM

// Host-side tensormap builder via driver entry point (no -lcuda needed)
typedef CUresult (*PFN_encodeTM)(CUtensorMap*, CUtensorMapDataType, cuuint32_t, void*,
                                 const cuuint64_t*, const cuuint64_t*, const cuuint32_t*,
                                 const cuuint32_t*, CUtensorMapInterleave, CUtensorMapSwizzle,
                                 CUtensorMapL2promotion, CUtensorMapFloatOOBfill);

static void make_map(CUtensorMap* m, const void* base,
                     unsigned long long d0, unsigned long long d1, unsigned long long d2,
                     unsigned long long s1b, unsigned long long s2b,
                     unsigned int b0, unsigned int b1)
{
    void* fp = nullptr;
    cudaDriverEntryPointQueryResult st;
    cudaGetDriverEntryPoint("cuTensorMapEncodeTiled", &fp, cudaEnableDefault, &st);
    PFN_encodeTM enc = (PFN_encodeTM)fp;
    cuuint64_t dims[3] = {d0, d1, d2};
    cuuint64_t str[2]  = {s1b, s2b};
    cuuint32_t box[3]  = {b0, b1, 1};
    cuuint32_t es[3]   = {1, 1, 1};
    enc(m, CU_TENSOR_MAP_DATA_TYPE_FLOAT32, 3, (void*)base, dims, str, box, es,
        CU_TENSOR_MAP_INTERLEAVE_NONE, CU_TENSOR_MAP_SWIZZLE_128B,
        CU_TENSOR_MAP_L2_PROMOTION_L2_128B, CU_TENSOR_MAP_FLOAT_OOB_FILL_NONE);
}

extern "C" void kernel_launch(void* const* d_in, const int* in_sizes, int n_in,
                              void* d_out, int out_size)
{
    const float* x     = (const float*)d_in[0];  // [B,S,E]
    const float* qkv_w = (const float*)d_in[1];  // [H,3E,E]
    const float* qkv_b = (const float*)d_in[2];  // [H,3E]
    const float* out_w = (const float*)d_in[3];  // [E,H*E]
    const float* out_b = (const float*)d_in[4];  // [E]
    float* out = (float*)d_out;                  // [B,S,E]

    float *qkv, *scores, *vT, *concat, *xr, *wr, *owr;
    cudaGetSymbolAddress((void**)&qkv,    g_qkv);
    cudaGetSymbolAddress((void**)&scores, g_scores);
    cudaGetSymbolAddress((void**)&vT,     g_vT);
    cudaGetSymbolAddress((void**)&concat, g_concat);
    cudaGetSymbolAddress((void**)&xr,     g_xr);
    cudaGetSymbolAddress((void**)&wr,     g_wqkvr);
    cudaGetSymbolAddress((void**)&owr,    g_owr);

    cudaFuncSetAttribute(gemm_tma<2,1,1,1>, cudaFuncAttributeMaxDynamicSharedMemorySize, SMEM_RING);
    cudaFuncSetAttribute(gemm_tma<2,0,0,0>, cudaFuncAttributeMaxDynamicSharedMemorySize, SMEM_RING);
    cudaFuncSetAttribute(gemm_tma<2,0,1,0>, cudaFuncAttributeMaxDynamicSharedMemorySize, SMEM_RING);

    // 0) Pre-round inputs to tf32 bits
    round_copy<<<(Bn*Sn*En/4 + 255)/256, 256>>>(x, xr, Bn*Sn*En/4);
    round_copy<<<(NQKV*En/4 + 255)/256, 256>>>(qkv_w, wr, NQKV*En/4);
    round_copy<<<(En*HE/4 + 255)/256, 256>>>(out_w, owr, En*HE/4);

    // Tensormaps (host-side, capture-safe)
    CUtensorMap mXA, mWB, mQA, mKB, mPA, mVB, mCA, mOB;
    make_map(&mXA, xr,      En, (unsigned long long)Bn*Sn, 1,
             (unsigned long long)En*4, (unsigned long long)Bn*Sn*En*4, 32, 128);
    make_map(&mWB, wr,      En, NQKV, 1,
             (unsigned long long)En*4, (unsigned long long)NQKV*En*4, 32, 256);
    make_map(&mQA, qkv,     En, Sn, Bn*Hn,
             (unsigned long long)F3*4, (unsigned long long)Sn*F3*4, 32, 128);
    make_map(&mKB, qkv+En,  En, Sn, Bn*Hn,
             (unsigned long long)F3*4, (unsigned long long)Sn*F3*4, 32, 256);
    make_map(&mPA, scores,  Sn, Sn, Bn*Hn,
             (unsigned long long)Sn*4, (unsigned long long)Sn*Sn*4, 32, 128);
    make_map(&mVB, vT,      Sn, En, Bn*Hn,
             (unsigned long long)Sn*4, (unsigned long long)En*Sn*4, 32, 256);
    make_map(&mCA, concat,  HE, (unsigned long long)Bn*Sn, 1,
             (unsigned long long)HE*4, (unsigned long long)Bn*Sn*HE*4, 32, 128);
    make_map(&mOB, owr,     HE, En, 1,
             (unsigned long long)HE*4, (unsigned long long)En*HE*4, 32, 256);

    // 1) QKV projection -> Q,K scatter to [B,H,S,3E]; V written transposed to vT.
    //    SWAP grid: bm on x so each wave spans all M tiles -> W streamed once.
    {
        GemmParams p = {};
        p.A = xr; p.B = wr; p.C = qkv;
        p.K = En; p.lda = En; p.ldb = En; p.ldc = 0;
        p.divH = 1; p.bias = qkv_b; p.alpha = 1.0f;
        gemm_tma<2,1,1,1><<<dim3((Bn*Sn)/128, NQKV/256, 1), 256, SMEM_RING>>>(mXA, mWB, p);
    }

    // 2) Scores: Q x K^T * scale. 128x256, 2-stage, 2 CTAs/SM.
    {
        GemmParams p = {};
        p.A = qkv; p.B = qkv + En; p.C = scores;
        p.K = En; p.lda = F3; p.ldb = F3; p.ldc = Sn;
        p.strideAz = (long long)Sn*F3; p.strideBz = (long long)Sn*F3;
        p.strideCb = (long long)Sn*Sn; p.divH = 1;
        p.bias = nullptr; p.alpha = 0.036084391824351615f; // 1/sqrt(768)
        gemm_tma<2,0,0,0><<<dim3(Sn/256, Sn/128, Bn*Hn), 256, SMEM_RING>>>(mQA, mKB, p);
    }

    // 3) Softmax rows (rounds output)
    softmax_kernel<<<Bn*Hn*Sn, 256>>>(scores);

    // 4) AV: P x vT^T -> concat, rounded.
    {
        GemmParams p = {};
        p.A = scores; p.B = vT; p.C = concat;
        p.K = Sn; p.lda = Sn; p.ldb = Sn; p.ldc = HE;
        p.strideAz = (long long)Sn*Sn; p.strideBz = (long long)En*Sn;
        p.strideCb = (long long)Sn*Hn*En; p.strideCh = En; p.divH = Hn;
        p.bias = nullptr; p.alpha = 1.0f;
        gemm_tma<2,0,1,0><<<dim3(En/256, Sn/128, Bn*Hn), 256, SMEM_RING>>>(mPA, mVB, p);
    }

    // 5) Output projection + bias -> out. 192 CTAs at 2/SM = single wave.
    {
        GemmParams p = {};
        p.A = concat; p.B = owr; p.C = out;
        p.K = HE; p.lda = HE; p.ldb = HE; p.ldc = En;
        p.divH = 1; p.bias = out_b; p.alpha = 1.0f;
        gemm_tma<2,0,0,0><<<dim3(En/256, (Bn*Sn)/128, 1), 256, SMEM_RING>>>(mCA, mOB, p);
    }
}

// round 17
// speedup vs baseline: 1.1836x; 1.1836x over previous
#include <cuda_runtime.h>
#include <cuda.h>
#include <stdint.h>

// Problem constants
#define Bn 8
#define Sn 1024
#define En 768
#define Hn 12
#define F3 2304          // 3*E
#define NQKV 27648       // H*3E
#define HE 9216          // H*E

// Scratch (allocation-free: __device__ globals)
__device__ float g_qkv[(size_t)Bn * Hn * Sn * F3];     // [B,H,S,3E] (Q,K slabs used)
__device__ float g_scores[(size_t)Bn * Hn * Sn * Sn];  // [B*H,S,S]
__device__ float g_vT[(size_t)Bn * Hn * En * Sn];      // [B*H,E,S]  (tf32-rounded)
__device__ float g_concat[(size_t)Bn * Sn * Hn * En];  // [B,S,H,E]  (tf32-rounded)
__device__ float g_xr[(size_t)Bn * Sn * En];           // rounded x
__device__ float g_wqkvr[(size_t)NQKV * En];           // rounded qkv_w
__device__ float g_owr[(size_t)En * HE];               // rounded out_w

struct GemmParams {
    const float* A;
    const float* B;
    float* C;
    int K;
    int lda, ldb, ldc;
    long long strideAz, strideBz;
    long long strideCb, strideCh;
    int divH;
    const float* bias;
    float alpha;
};

__device__ __forceinline__ uint32_t f2tf32(float x) {
    uint32_t r;
    asm("cvt.rna.tf32.f32 %0, %1;" : "=r"(r) : "f"(x));
    return r;
}

__device__ __forceinline__ uint32_t smem_u32_g(const void* p) {
    uint32_t a;
    asm("{ .reg .u64 t; cvta.to.shared.u64 t, %1; cvt.u32.u64 %0, t; }"
        : "=r"(a) : "l"(p));
    return a;
}

#if defined(__CUDA_ARCH_FEAT_SM103_ALL)
// ---------- sm_103a-only helpers ----------
__device__ __forceinline__ uint32_t elect_one() {
    uint32_t p;
    asm volatile(
        "{\n\t.reg .pred p;\n\telect.sync _|p, 0xFFFFFFFF;\n\t"
        "selp.b32 %0, 1, 0, p;\n\t}" : "=r"(p));
    return p;
}

__device__ __forceinline__ uint32_t ctarank() {
    uint32_t r;
    asm("mov.u32 %0, %%cluster_ctarank;" : "=r"(r));
    return r;
}

#define TCGEN05_ALLOC(a, n) \
    asm volatile("tcgen05.alloc.cta_group::1.sync.aligned.shared::cta.b32 [%0], %1;" \
                 :: "r"(a), "r"(n) : "memory")
#define TCGEN05_DEALLOC(t, n) \
    asm volatile("tcgen05.dealloc.cta_group::1.sync.aligned.b32 %0, %1;" :: "r"(t), "r"(n))
#define TCGEN05_RELINQ() \
    asm volatile("tcgen05.relinquish_alloc_permit.cta_group::1.sync.aligned;")
#define TCGEN05_COMMIT(m) \
    asm volatile("tcgen05.commit.cta_group::1.mbarrier::arrive::one.shared::cluster.b64 [%0];" \
                 :: "r"(m) : "memory")
#define TCGEN05_ALLOC_CG2(a, n) \
    asm volatile("tcgen05.alloc.cta_group::2.sync.aligned.shared::cta.b32 [%0], %1;" \
                 :: "r"(a), "r"(n) : "memory")
#define TCGEN05_DEALLOC_CG2(t, n) \
    asm volatile("tcgen05.dealloc.cta_group::2.sync.aligned.b32 %0, %1;" :: "r"(t), "r"(n))
#define TCGEN05_RELINQ_CG2() \
    asm volatile("tcgen05.relinquish_alloc_permit.cta_group::2.sync.aligned;")
#define TCGEN05_COMMIT_MC_CG2(m, mask) \
    asm volatile("tcgen05.commit.cta_group::2.mbarrier::arrive::one.shared::cluster.multicast::cluster.b64 [%0], %1;" \
                 :: "r"(m), "h"((uint16_t)(mask)) : "memory")
#define MBARRIER_INIT(m, c) \
    asm volatile("mbarrier.init.shared.b64 [%0], %1;" :: "r"(m), "r"(c) : "memory")
#define MBARRIER_INVAL(m) \
    asm volatile("mbarrier.inval.shared.b64 [%0];" :: "r"(m) : "memory")
#define MBARRIER_EXPECT_TX(m, b) \
    asm volatile("mbarrier.arrive.expect_tx.shared.b64 _, [%0], %1;" \
                 :: "r"(m), "r"(b) : "memory")
#define MBARRIER_ARRIVE_CLUSTER(m, rank) \
    asm volatile( \
        "{\n\t.reg .b32 ra;\n\t" \
        "mapa.shared::cluster.u32 ra, %0, %1;\n\t" \
        "mbarrier.arrive.shared::cluster.b64 _, [ra];\n\t}" \
        :: "r"(m), "r"(rank) : "memory")
#define CLUSTER_SYNC() do { \
    asm volatile("barrier.cluster.arrive.aligned;" ::: "memory"); \
    asm volatile("barrier.cluster.wait.aligned;" ::: "memory"); \
} while (0)
#define TCGEN05_FENCE_AFTER()  asm volatile("tcgen05.fence::after_thread_sync;" ::: "memory")
#define TCGEN05_FENCE_BEFORE() asm volatile("tcgen05.fence::before_thread_sync;" ::: "memory")
#define TCGEN05_WAIT_LD()      asm volatile("tcgen05.wait::ld.sync.aligned;" ::: "memory")
#define FENCE_ASYNC()          asm volatile("fence.proxy.async.shared::cta;" ::: "memory")

#define TMA3D(sm, mapp, cx, cy, cz, mb) \
    asm volatile( \
        "cp.async.bulk.tensor.3d.shared::cta.global.tile.mbarrier::complete_tx::bytes " \
        "[%0], [%1, {%2, %3, %4}], [%5];" \
        :: "r"(sm), "l"(mapp), "r"(cx), "r"(cy), "r"(cz), "r"(mb) : "memory")

#define MBARRIER_WAIT_PARITY(mbar_smem_addr, phase_parity) do { \
    uint32_t _mbar = (uint32_t)(mbar_smem_addr); \
    uint32_t _parity = (uint32_t)(phase_parity); \
    uint32_t _done; \
    asm volatile( \
        "{\n\t.reg .pred p;\n\t" \
        "mbarrier.try_wait.parity.acquire.cta.shared::cta.b64 p, [%1], %2;\n\t" \
        "selp.b32 %0, 1, 0, p;\n\t}" \
        : "=r"(_done) : "r"(_mbar), "r"(_parity) : "memory"); \
    if (!_done) { \
        asm volatile( \
            "{\n\t.reg .pred P1;\n\t" \
            "WAIT_LOOP_%=:\n\t" \
            "mbarrier.try_wait.parity.acquire.cta.shared::cta.b64 P1, [%0], %1, 0x989680;\n\t" \
            "@P1 bra.uni WAIT_DONE_%=;\n\t" \
            "bra.uni WAIT_LOOP_%=;\n\t" \
            "WAIT_DONE_%=:\n\t}" \
            :: "r"(_mbar), "r"(_parity) : "memory"); \
    } \
} while (0)

#define TCGEN05_LD_32X32B_X32(r, tmem_addr) \
    asm volatile( \
        "tcgen05.ld.sync.aligned.32x32b.x32.b32 " \
        "{%0, %1, %2, %3, %4, %5, %6, %7, " \
        " %8, %9, %10, %11, %12, %13, %14, %15, " \
        " %16, %17, %18, %19, %20, %21, %22, %23, " \
        " %24, %25, %26, %27, %28, %29, %30, %31}, [%32];" \
        : "=r"((r)[0]),  "=r"((r)[1]),  "=r"((r)[2]),  "=r"((r)[3]), \
          "=r"((r)[4]),  "=r"((r)[5]),  "=r"((r)[6]),  "=r"((r)[7]), \
          "=r"((r)[8]),  "=r"((r)[9]),  "=r"((r)[10]), "=r"((r)[11]), \
          "=r"((r)[12]), "=r"((r)[13]), "=r"((r)[14]), "=r"((r)[15]), \
          "=r"((r)[16]), "=r"((r)[17]), "=r"((r)[18]), "=r"((r)[19]), \
          "=r"((r)[20]), "=r"((r)[21]), "=r"((r)[22]), "=r"((r)[23]), \
          "=r"((r)[24]), "=r"((r)[25]), "=r"((r)[26]), "=r"((r)[27]), \
          "=r"((r)[28]), "=r"((r)[29]), "=r"((r)[30]), "=r"((r)[31]) \
        : "r"(tmem_addr))

// SW128 K-major SMEM descriptor (128B rows): layout=SW128, version=1, SBO=64, LBO=1
static __device__ __forceinline__ uint64_t mk_desc(uint32_t addr) {
    const uint64_t base = (2ULL << 61) | (1ULL << 46) | (64ULL << 32) | (1ULL << 16);
    return base | ((uint64_t)(addr >> 4) & 0x3FFF);
}

// idesc kind::tf32: dtype F32=1 @bit4, atype=btype=TF32=2 @bits7/10,
// N/8 @bits[17:23) (6 bits, N<=504!), M/16 @bit24
#define IDESC_TF32     ((1u << 4) | (2u << 7) | (2u << 10) | (32u << 17) | (8u << 24))
#define IDESC_TF32_CG2 ((1u << 4) | (2u << 7) | (2u << 10) | (32u << 17) | (16u << 24))

__device__ __forceinline__ void mma_tf32_ss(uint32_t d_tmem, uint64_t ad, uint64_t bd,
                                            uint32_t en) {
    asm volatile(
        "{\n\t.reg .pred pq;\n\tsetp.ne.u32 pq, %5, 0;\n\t"
        "tcgen05.mma.cta_group::1.kind::tf32 [%0], %1, %2, %3, {%4, %4, %4, %4}, pq;\n\t}"
        :: "r"(d_tmem), "l"(ad), "l"(bd), "r"(IDESC_TF32), "r"(0u), "r"(en)
        : "memory");
}

// cg2 MMA: M=256 (128 rows per CTA), N=256 (128 B-rows per CTA at same offset)
__device__ __forceinline__ void mma_tf32_ss_cg2(uint32_t d_tmem, uint64_t ad, uint64_t bd,
                                                uint32_t en) {
    asm volatile(
        "{\n\t.reg .pred pq;\n\tsetp.ne.u32 pq, %5, 0;\n\t"
        "tcgen05.mma.cta_group::2.kind::tf32 [%0], %1, %2, %3, "
        "{%4, %4, %4, %4, %4, %4, %4, %4}, pq;\n\t}"
        :: "r"(d_tmem), "l"(ad), "l"(bd), "r"(IDESC_TF32_CG2), "r"(0u), "r"(en)
        : "memory");
}
#endif  // __CUDA_ARCH_FEAT_SM103_ALL

// ---------- single-CTA GEMM (R14-proven): tile (128*MH)x256 ----------
template <int MH, int NS, int EPI, int ROUND, int SWAP>
__global__ void __launch_bounds__(256) gemm_tma(
    const __grid_constant__ CUtensorMap mA,
    const __grid_constant__ CUtensorMap mB,
    GemmParams p)
{
    extern __shared__ __align__(16) float smem_raw[];
    const int tid = threadIdx.x;
    const int lane = tid & 31;
    const int wid = tid >> 5;
    const int bn = SWAP ? blockIdx.y : blockIdx.x;
    const int bm = SWAP ? blockIdx.x : blockIdx.y;
    const int z  = blockIdx.z;
    const size_t coff = (size_t)(z / p.divH) * p.strideCb +
                        (size_t)(z % p.divH) * p.strideCh;

#if defined(__CUDA_ARCH_FEAT_SM103_ALL)
    __shared__ uint32_t s_tmem;
    __shared__ __align__(8) unsigned long long s_mbar[2 * NS];

    const uint32_t raw_u  = smem_u32_g(smem_raw);
    const uint32_t smem_u = (raw_u + 1023u) & ~1023u;
    float* smem_al = (float*)((char*)smem_raw + (smem_u - raw_u));
    const uint32_t mbar   = smem_u32_g(s_mbar);

    constexpr uint32_t ASZ = MH * 16384u;
    constexpr uint32_t SZ  = ASZ + 32768u;
    constexpr uint32_t TCOLS = MH * 256u;

    if (wid == 0) { TCGEN05_ALLOC(smem_u32_g(&s_tmem), TCOLS); TCGEN05_RELINQ(); }
    if (tid == 0) {
        #pragma unroll
        for (int s = 0; s < 2 * NS; s++) MBARRIER_INIT(mbar + 8 * s, 1);
        FENCE_ASYNC();
    }
    __syncthreads();
    const uint32_t tmem = s_tmem;
    const int nIter = p.K >> 5;

    if (wid == 0) {
        if (elect_one()) {
            const CUtensorMap* pA = &mA;
            const CUtensorMap* pB = &mB;
            const int m0 = bm * (128 * MH);
            const int n0 = bn * 256;
            int phf[NS], phd[NS];
            #pragma unroll
            for (int s = 0; s < NS; s++) { phf[s] = 0; phd[s] = 0; }

            const int pre = (nIter < NS) ? nIter : NS;
            for (int s = 0; s < pre; s++) {
                MBARRIER_EXPECT_TX(mbar + 8 * s, SZ);
                TMA3D(smem_u + s * SZ, pA, s * 32, m0, z, mbar + 8 * s);
                TMA3D(smem_u + s * SZ + ASZ, pB, s * 32, n0, z, mbar + 8 * s);
            }
            for (int kt = 0; kt < nIter; kt++) {
                const int b = kt % NS;
                MBARRIER_WAIT_PARITY(mbar + 8 * b, phf[b]); phf[b] ^= 1;
                const uint32_t oa = smem_u + b * SZ;
                const uint64_t bd = mk_desc(oa + ASZ);
                #pragma unroll
                for (int ks = 0; ks < 4; ks++) {
                    #pragma unroll
                    for (int mh = 0; mh < MH; mh++) {
                        const uint64_t ad = mk_desc(oa + mh * 16384u);
                        mma_tf32_ss(tmem + mh * 256, ad + ks * 2, bd + ks * 2,
                                    (kt > 0 || ks > 0) ? 1u : 0u);
                    }
                }
                TCGEN05_COMMIT(mbar + 8 * (NS + b));
                const int rt = kt - 1;
                if (rt >= 0 && rt + NS < nIter) {
                    const int rb = rt % NS;
                    MBARRIER_WAIT_PARITY(mbar + 8 * (NS + rb), phd[rb]); phd[rb] ^= 1;
                    const uint32_t ra = smem_u + rb * SZ;
                    MBARRIER_EXPECT_TX(mbar + 8 * rb, SZ);
                    TMA3D(ra, pA, (rt + NS) * 32, m0, z, mbar + 8 * rb);
                    TMA3D(ra + ASZ, pB, (rt + NS) * 32, n0, z, mbar + 8 * rb);
                }
            }
            int first = nIter - NS;
            if (first < 0) first = 0;
            for (int kt = first; kt < nIter; kt++) {
                const int b = kt % NS;
                MBARRIER_WAIT_PARITY(mbar + 8 * (NS + b), phd[b]); phd[b] ^= 1;
            }
        }
    }
    __syncthreads();
    TCGEN05_FENCE_AFTER();

    const int nslice = (MH == 2) ? 8 : 4;
    const int mrow0 = bm * (128 * MH) +
                      ((MH == 2) ? (wid >> 2) * 128 : 0) + (wid & 3) * 32;
    const uint32_t tbase = tmem + ((MH == 2) ? (uint32_t)(wid >> 2) * 256u
                                             : (uint32_t)(wid >> 2) * 128u);
    const int nbase = bn * 256 + ((MH == 2) ? 0 : (wid >> 2) * 128);
    float* stg = smem_al + wid * (33 * 32);

    for (int i = 0; i < nslice; i++) {
        uint32_t r[32];
        TCGEN05_LD_32X32B_X32(r, tbase + i * 32);
        TCGEN05_WAIT_LD();
        #pragma unroll
        for (int j = 0; j < 32; j++) stg[lane * 33 + j] = __uint_as_float(r[j]);
        __syncwarp();

        const int n0 = nbase + i * 32;
        if (EPI == 1) {
            const int b = mrow0 >> 10, s = mrow0 & 1023;
            const int h = n0 / F3, f = n0 - h * F3;
            if (f >= 2 * En) {
                float* dstv = g_vT + (((size_t)(b * Hn + h)) * En + (f - 2 * En)) * Sn + s;
                #pragma unroll 8
                for (int row = 0; row < 32; row++) {
                    float bia = p.bias ? __ldg(&p.bias[n0 + row]) : 0.f;
                    float v = stg[lane * 33 + row] * p.alpha + bia;
                    if (ROUND) v = __uint_as_float(f2tf32(v));
                    dstv[(size_t)row * Sn + lane] = v;
                }
                __syncwarp();
                continue;
            }
        }
        const float bia = p.bias ? __ldg(&p.bias[n0 + lane]) : 0.f;
        float* dst0;
        long long rstride;
        if (EPI == 1) {
            const int b = mrow0 >> 10, s = mrow0 & 1023;
            const int h = n0 / F3, f = n0 - h * F3;
            dst0 = &g_qkv[(((size_t)(b * Hn + h)) * Sn + s) * F3 + f];
            rstride = F3;
        } else {
            dst0 = &p.C[coff + (size_t)mrow0 * p.ldc + n0];
            rstride = p.ldc;
        }
        #pragma unroll 8
        for (int row = 0; row < 32; row++) {
            float v = stg[row * 33 + lane] * p.alpha + bia;
            if (ROUND) v = __uint_as_float(f2tf32(v));
            dst0[(size_t)row * rstride + lane] = v;
        }
        __syncwarp();
    }
    TCGEN05_FENCE_BEFORE();

    __syncthreads();
    if (tid == 0) {
        #pragma unroll
        for (int s = 0; s < 2 * NS; s++) MBARRIER_INVAL(mbar + 8 * s);
    }
    __syncthreads();
    if (wid == 0) TCGEN05_DEALLOC(tmem, TCOLS);

#else
    (void)smem_raw;
    const int MT = 128 * MH;
    for (int o = tid; o < MT * 256; o += 256) {
        const int mi = o >> 8;
        const int ni = o & 255;
        const float* a = p.A + (size_t)z * p.strideAz + (size_t)(bm * MT + mi) * p.lda;
        const float* b = p.B + (size_t)z * p.strideBz + (size_t)(bn * 256 + ni) * p.ldb;
        float acc = 0.f;
        for (int k = 0; k < p.K; k++) acc += a[k] * b[k];
        float v = acc * p.alpha;
        const int n0 = bn * 256 + ni;
        if (p.bias) v += p.bias[n0];
        if (ROUND) v = __uint_as_float(f2tf32(v));
        const int mg = bm * MT + mi;
        if (EPI == 1) {
            const int bb = mg >> 10, s = mg & 1023;
            const int h = n0 / F3, f = n0 - h * F3;
            if (f >= 2 * En)
                g_vT[(((size_t)(bb * Hn + h)) * En + (f - 2 * En)) * Sn + s] = v;
            else
                g_qkv[(((size_t)(bb * Hn + h)) * Sn + s) * F3 + f] = v;
        } else {
            p.C[coff + (size_t)mg * p.ldc + n0] = v;
        }
    }
#endif
}

// ---------- cg2 QKV GEMM: pair tile 256x512 via TWO cg2 MMAs (M=256,N=256) ----------
// Cluster (2,1,1). CTA bx holds A rows [bx*128, +128); pair covers 256 rows.
// Per n-half j (0,1): CTA rank r loads B rows by*512 + j*256 + r*128 at SMEM
// offset ASZ + j*16K (HW reads 128 rows from each CTA at the same offset).
// rank0 issues both cg2 MMAs into TMEM cols j*256; commit multicast to both
// CTAs' done bars; rank1 signals data-ready via mapa arrive to rank0 peer bar.
__global__ void __launch_bounds__(256) gemm_cg2_qkv(
    const __grid_constant__ CUtensorMap mA,
    const __grid_constant__ CUtensorMap mB,
    GemmParams p)
{
    extern __shared__ __align__(16) float smem_raw[];
    const int tid = threadIdx.x;
    const int lane = tid & 31;
    const int wid = tid >> 5;
    const int bx = blockIdx.x;     // 0..63
    const int by = blockIdx.y;     // 0..53

#if defined(__CUDA_ARCH_FEAT_SM103_ALL)
    constexpr int NS = 3;
    __shared__ uint32_t s_tmem;
    __shared__ __align__(8) unsigned long long s_mbar[3 * NS];  // full, done, peer

    const uint32_t raw_u  = smem_u32_g(smem_raw);
    const uint32_t smem_u = (raw_u + 1023u) & ~1023u;
    float* smem_al = (float*)((char*)smem_raw + (smem_u - raw_u));
    const uint32_t mbar = smem_u32_g(s_mbar);
    const uint32_t rank = ctarank();

    constexpr uint32_t ASZ = 16384u;            // A: 128 rows x 128B
    constexpr uint32_t BH  = 16384u;            // one B half-chunk: 128 rows
    constexpr uint32_t SZ  = ASZ + 2 * BH;      // 48KB per stage

    if (wid == 0) { TCGEN05_ALLOC_CG2(smem_u32_g(&s_tmem), 512); TCGEN05_RELINQ_CG2(); }
    if (tid == 0) {
        #pragma unroll
        for (int s = 0; s < 3 * NS; s++) MBARRIER_INIT(mbar + 8 * s, 1);
        FENCE_ASYNC();
    }
    __syncthreads();
    CLUSTER_SYNC();   // peer bars must be initialized before remote arrivals
    const uint32_t tmem = s_tmem;

    const int nIter = 24;          // K=768
    const int m0  = bx * 128;
    const int nb0 = by * 512 + (int)rank * 128;          // B rows, n-half 0
    const int nb1 = by * 512 + 256 + (int)rank * 128;    // B rows, n-half 1

    if (wid == 0) {
        if (elect_one()) {
            const CUtensorMap* pA = &mA;
            const CUtensorMap* pB = &mB;
            int phf[NS], phd[NS], php[NS];
            #pragma unroll
            for (int s = 0; s < NS; s++) { phf[s] = 0; phd[s] = 0; php[s] = 0; }

            for (int s = 0; s < NS; s++) {
                MBARRIER_EXPECT_TX(mbar + 8 * s, SZ);
                TMA3D(smem_u + s * SZ, pA, s * 32, m0, 0, mbar + 8 * s);
                TMA3D(smem_u + s * SZ + ASZ, pB, s * 32, nb0, 0, mbar + 8 * s);
                TMA3D(smem_u + s * SZ + ASZ + BH, pB, s * 32, nb1, 0, mbar + 8 * s);
            }

            for (int kt = 0; kt < nIter; kt++) {
                const int b = kt % NS;
                MBARRIER_WAIT_PARITY(mbar + 8 * b, phf[b]); phf[b] ^= 1;
                if (rank == 1) {
                    MBARRIER_ARRIVE_CLUSTER(mbar + 8 * (2 * NS + b), 0);
                } else {
                    MBARRIER_WAIT_PARITY(mbar + 8 * (2 * NS + b), php[b]); php[b] ^= 1;
                    const uint32_t oa = smem_u + b * SZ;
                    const uint64_t ad = mk_desc(oa);
                    #pragma unroll
                    for (int j = 0; j < 2; j++) {
                        const uint64_t bd = mk_desc(oa + ASZ + j * BH);
                        #pragma unroll
                        for (int ks = 0; ks < 4; ks++)
                            mma_tf32_ss_cg2(tmem + j * 256, ad + ks * 2, bd + ks * 2,
                                            (kt > 0 || ks > 0) ? 1u : 0u);
                    }
                    TCGEN05_COMMIT_MC_CG2(mbar + 8 * (NS + b), 0x3);
                }
                const int rt = kt - 1;
                if (rt >= 0 && rt + NS < nIter) {
                    const int rb = rt % NS;
                    MBARRIER_WAIT_PARITY(mbar + 8 * (NS + rb), phd[rb]); phd[rb] ^= 1;
                    const uint32_t ra = smem_u + rb * SZ;
                    MBARRIER_EXPECT_TX(mbar + 8 * rb, SZ);
                    TMA3D(ra, pA, (rt + NS) * 32, m0, 0, mbar + 8 * rb);
                    TMA3D(ra + ASZ, pB, (rt + NS) * 32, nb0, 0, mbar + 8 * rb);
                    TMA3D(ra + ASZ + BH, pB, (rt + NS) * 32, nb1, 0, mbar + 8 * rb);
                }
            }
            for (int kt = nIter - NS; kt < nIter; kt++) {
                const int b = kt % NS;
                MBARRIER_WAIT_PARITY(mbar + 8 * (NS + b), phd[b]); phd[b] ^= 1;
            }
        }
    }
    __syncthreads();
    TCGEN05_FENCE_AFTER();

    // Epilogue: this CTA's TMEM = its 128 M-rows x 512 cols
    // (cols [0,256) = n-half 0, [256,512) = n-half 1).
    const int mrow0 = bx * 128 + (wid & 3) * 32;
    const uint32_t tbase = tmem + (uint32_t)(wid >> 2) * 256u;
    const int nbase = by * 512 + (wid >> 2) * 256;
    float* stg = smem_al + wid * (33 * 32);

    for (int i = 0; i < 8; i++) {
        uint32_t r[32];
        TCGEN05_LD_32X32B_X32(r, tbase + i * 32);
        TCGEN05_WAIT_LD();
        #pragma unroll
        for (int j = 0; j < 32; j++) stg[lane * 33 + j] = __uint_as_float(r[j]);
        __syncwarp();

        const int n0c = nbase + i * 32;
        const int b = mrow0 >> 10, s = mrow0 & 1023;
        const int h = n0c / F3, f = n0c - h * F3;
        if (f >= 2 * En) {
            float* dstv = g_vT + (((size_t)(b * Hn + h)) * En + (f - 2 * En)) * Sn + s;
            #pragma unroll 8
            for (int row = 0; row < 32; row++) {
                float bia = __ldg(&p.bias[n0c + row]);
                float v = __uint_as_float(f2tf32(stg[lane * 33 + row] + bia));
                dstv[(size_t)row * Sn + lane] = v;
            }
        } else {
            const float bia = __ldg(&p.bias[n0c + lane]);
            float* dst0 = &g_qkv[(((size_t)(b * Hn + h)) * Sn + s) * F3 + f];
            #pragma unroll 8
            for (int row = 0; row < 32; row++) {
                float v = __uint_as_float(f2tf32(stg[row * 33 + lane] + bia));
                dst0[(size_t)row * F3 + lane] = v;
            }
        }
        __syncwarp();
    }
    TCGEN05_FENCE_BEFORE();

    __syncthreads();
    if (tid == 0) {
        #pragma unroll
        for (int s = 0; s < 3 * NS; s++) MBARRIER_INVAL(mbar + 8 * s);
    }
    __syncthreads();
    if (wid == 0) TCGEN05_DEALLOC_CG2(tmem, 512);
    CLUSTER_SYNC();

#else
    // Naive correct fallback (matches cg2 tile mapping)
    (void)smem_raw;
    for (int o = tid; o < 128 * 512; o += 256) {
        const int mi = o >> 9;
        const int ni = o & 511;
        const int mg = bx * 128 + mi;
        const int n0c = by * 512 + ni;
        const float* a = p.A + (size_t)mg * p.lda;
        const float* b = p.B + (size_t)n0c * p.ldb;
        float acc = 0.f;
        for (int k = 0; k < p.K; k++) acc += a[k] * b[k];
        float v = acc + p.bias[n0c];
        v = __uint_as_float(f2tf32(v));
        const int bb = mg >> 10, s = mg & 1023;
        const int h = n0c / F3, f = n0c - h * F3;
        if (f >= 2 * En)
            g_vT[(((size_t)(bb * Hn + h)) * En + (f - 2 * En)) * Sn + s] = v;
        else
            g_qkv[(((size_t)(bb * Hn + h)) * Sn + s) * F3 + f] = v;
    }
#endif
}

// Round-copy: dst = tf32_rna(src)
__global__ void __launch_bounds__(256) round_copy(const float* __restrict__ s,
                                                  float* __restrict__ d, int n4)
{
    int i = blockIdx.x * blockDim.x + threadIdx.x;
    if (i < n4) {
        float4 v = ((const float4*)s)[i];
        uint4 o;
        o.x = f2tf32(v.x); o.y = f2tf32(v.y); o.z = f2tf32(v.z); o.w = f2tf32(v.w);
        ((uint4*)d)[i] = o;
    }
}

// Softmax rows; output rounded to tf32 bits (AV GEMM input).
__global__ void __launch_bounds__(256) softmax_kernel(float* sc)
{
    float* row = sc + (size_t)blockIdx.x * Sn;
    const int tid = threadIdx.x;
    const int lane = tid & 31;
    const int wid = tid >> 5;
    __shared__ float red[8];

    float4 v = ((const float4*)row)[tid];
    float m = fmaxf(fmaxf(v.x, v.y), fmaxf(v.z, v.w));
    #pragma unroll
    for (int o = 16; o; o >>= 1) m = fmaxf(m, __shfl_xor_sync(~0u, m, o));
    if (lane == 0) red[wid] = m;
    __syncthreads();
    float bm = red[0];
    #pragma unroll
    for (int i = 1; i < 8; i++) bm = fmaxf(bm, red[i]);
    __syncthreads();

    float4 e;
    e.x = __expf(v.x - bm);
    e.y = __expf(v.y - bm);
    e.z = __expf(v.z - bm);
    e.w = __expf(v.w - bm);
    float s = e.x + e.y + e.z + e.w;
    #pragma unroll
    for (int o = 16; o; o >>= 1) s += __shfl_xor_sync(~0u, s, o);
    if (lane == 0) red[wid] = s;
    __syncthreads();
    float bs = red[0];
    #pragma unroll
    for (int i = 1; i < 8; i++) bs += red[i];
    const float rdiv = __frcp_rn(bs);

    uint4 o;
    o.x = f2tf32(e.x * rdiv);
    o.y = f2tf32(e.y * rdiv);
    o.z = f2tf32(e.z * rdiv);
    o.w = f2tf32(e.w * rdiv);
    ((uint4*)row)[tid] = o;
}

#define SMEM_RING (196608 + 1024)   // 3x64KB + align slack (single-CTA path)
#define SMEM_CG2  (147456 + 1024)   // 3x48KB + align slack (cg2 path)

// Host-side tensormap builder via driver entry point (no -lcuda needed)
typedef CUresult (*PFN_encodeTM)(CUtensorMap*, CUtensorMapDataType, cuuint32_t, void*,
                                 const cuuint64_t*, const cuuint64_t*, const cuuint32_t*,
                                 const cuuint32_t*, CUtensorMapInterleave, CUtensorMapSwizzle,
                                 CUtensorMapL2promotion, CUtensorMapFloatOOBfill);

static void make_map(CUtensorMap* m, const void* base,
                     unsigned long long d0, unsigned long long d1, unsigned long long d2,
                     unsigned long long s1b, unsigned long long s2b,
                     unsigned int b0, unsigned int b1)
{
    void* fp = nullptr;
    cudaDriverEntryPointQueryResult st;
    cudaGetDriverEntryPoint("cuTensorMapEncodeTiled", &fp, cudaEnableDefault, &st);
    PFN_encodeTM enc = (PFN_encodeTM)fp;
    cuuint64_t dims[3] = {d0, d1, d2};
    cuuint64_t str[2]  = {s1b, s2b};
    cuuint32_t box[3]  = {b0, b1, 1};
    cuuint32_t es[3]   = {1, 1, 1};
    enc(m, CU_TENSOR_MAP_DATA_TYPE_FLOAT32, 3, (void*)base, dims, str, box, es,
        CU_TENSOR_MAP_INTERLEAVE_NONE, CU_TENSOR_MAP_SWIZZLE_128B,
        CU_TENSOR_MAP_L2_PROMOTION_L2_128B, CU_TENSOR_MAP_FLOAT_OOB_FILL_NONE);
}

extern "C" void kernel_launch(void* const* d_in, const int* in_sizes, int n_in,
                              void* d_out, int out_size)
{
    const float* x     = (const float*)d_in[0];  // [B,S,E]
    const float* qkv_w = (const float*)d_in[1];  // [H,3E,E]
    const float* qkv_b = (const float*)d_in[2];  // [H,3E]
    const float* out_w = (const float*)d_in[3];  // [E,H*E]
    const float* out_b = (const float*)d_in[4];  // [E]
    float* out = (float*)d_out;                  // [B,S,E]

    float *qkv, *scores, *vT, *concat, *xr, *wr, *owr;
    cudaGetSymbolAddress((void**)&qkv,    g_qkv);
    cudaGetSymbolAddress((void**)&scores, g_scores);
    cudaGetSymbolAddress((void**)&vT,     g_vT);
    cudaGetSymbolAddress((void**)&concat, g_concat);
    cudaGetSymbolAddress((void**)&xr,     g_xr);
    cudaGetSymbolAddress((void**)&wr,     g_wqkvr);
    cudaGetSymbolAddress((void**)&owr,    g_owr);

    cudaFuncSetAttribute(gemm_cg2_qkv,        cudaFuncAttributeMaxDynamicSharedMemorySize, SMEM_CG2);
    cudaFuncSetAttribute(gemm_tma<2,3,0,0,0>, cudaFuncAttributeMaxDynamicSharedMemorySize, SMEM_RING);
    cudaFuncSetAttribute(gemm_tma<2,3,0,1,0>, cudaFuncAttributeMaxDynamicSharedMemorySize, SMEM_RING);

    // 0) Pre-round inputs to tf32 bits
    round_copy<<<(Bn*Sn*En/4 + 255)/256, 256>>>(x, xr, Bn*Sn*En/4);
    round_copy<<<(NQKV*En/4 + 255)/256, 256>>>(qkv_w, wr, NQKV*En/4);
    round_copy<<<(En*HE/4 + 255)/256, 256>>>(out_w, owr, En*HE/4);

    // Tensormaps (host-side, capture-safe)
    CUtensorMap mXA, mWB, mQA, mKB, mPA, mVB, mCA, mOB;
    make_map(&mXA, xr,      En, (unsigned long long)Bn*Sn, 1,
             (unsigned long long)En*4, (unsigned long long)Bn*Sn*En*4, 32, 128);
    make_map(&mWB, wr,      En, NQKV, 1,
             (unsigned long long)En*4, (unsigned long long)NQKV*En*4, 32, 128);
    make_map(&mQA, qkv,     En, Sn, Bn*Hn,
             (unsigned long long)F3*4, (unsigned long long)Sn*F3*4, 32, 256);
    make_map(&mKB, qkv+En,  En, Sn, Bn*Hn,
             (unsigned long long)F3*4, (unsigned long long)Sn*F3*4, 32, 256);
    make_map(&mPA, scores,  Sn, Sn, Bn*Hn,
             (unsigned long long)Sn*4, (unsigned long long)Sn*Sn*4, 32, 256);
    make_map(&mVB, vT,      Sn, En, Bn*Hn,
             (unsigned long long)Sn*4, (unsigned long long)En*Sn*4, 32, 256);
    make_map(&mCA, concat,  HE, (unsigned long long)Bn*Sn, 1,
             (unsigned long long)HE*4, (unsigned long long)Bn*Sn*HE*4, 32, 256);
    make_map(&mOB, owr,     HE, En, 1,
             (unsigned long long)HE*4, (unsigned long long)En*HE*4, 32, 256);

    // 1) QKV projection via cg2 pair tiles 256x512 (two N=256 MMAs);
    //    V written transposed to vT.
    {
        GemmParams p = {};
        p.A = xr; p.B = wr; p.C = qkv;
        p.K = En; p.lda = En; p.ldb = En; p.ldc = 0;
        p.divH = 1; p.bias = qkv_b; p.alpha = 1.0f;

        cudaLaunchConfig_t cfg = {};
        cfg.gridDim  = {(unsigned)((Bn * Sn) / 128), (unsigned)(NQKV / 512), 1};
        cfg.blockDim = {256, 1, 1};
        cfg.dynamicSmemBytes = SMEM_CG2;
        cudaLaunchAttribute attrs[1];
        attrs[0].id = cudaLaunchAttributeClusterDimension;
        attrs[0].val.clusterDim = {2, 1, 1};
        cfg.attrs = attrs;
        cfg.numAttrs = 1;
        cudaLaunchKernelEx(&cfg, gemm_cg2_qkv, mXA, mWB, p);
    }

    // 2) Scores: Q x K^T * scale. 256x256, 3-stage (R14-proven).
    {
        GemmParams p = {};
        p.A = qkv; p.B = qkv + En; p.C = scores;
        p.K = En; p.lda = F3; p.ldb = F3; p.ldc = Sn;
        p.strideAz = (long long)Sn*F3; p.strideBz = (long long)Sn*F3;
        p.strideCb = (long long)Sn*Sn; p.divH = 1;
        p.bias = nullptr; p.alpha = 0.036084391824351615f; // 1/sqrt(768)
        gemm_tma<2,3,0,0,0><<<dim3(Sn/256, Sn/256, Bn*Hn), 256, SMEM_RING>>>(mQA, mKB, p);
    }

    // 3) Softmax rows (rounds output)
    softmax_kernel<<<Bn*Hn*Sn, 256>>>(scores);

    // 4) AV: P x vT^T -> concat, rounded. 256x256, 3-stage.
    {
        GemmParams p = {};
        p.A = scores; p.B = vT; p.C = concat;
        p.K = Sn; p.lda = Sn; p.ldb = Sn; p.ldc = HE;
        p.strideAz = (long long)Sn*Sn; p.strideBz = (long long)En*Sn;
        p.strideCb = (long long)Sn*Hn*En; p.strideCh = En; p.divH = Hn;
        p.bias = nullptr; p.alpha = 1.0f;
        gemm_tma<2,3,0,1,0><<<dim3(En/256, Sn/256, Bn*Hn), 256, SMEM_RING>>>(mPA, mVB, p);
    }

    // 5) Output projection + bias -> out. 256x256 tiles: 96 CTAs = one wave.
    {
        GemmParams p = {};
        p.A = concat; p.B = owr; p.C = out;
        p.K = HE; p.lda = HE; p.ldb = HE; p.ldc = En;
        p.divH = 1; p.bias = out_b; p.alpha = 1.0f;
        gemm_tma<2,3,0,0,0><<<dim3(En/256, (Bn*Sn)/256, 1), 256, SMEM_RING>>>(mCA, mOB, p);
    }
}